// round 8
// baseline (speedup 1.0000x reference)
#include <cuda_runtime.h>

// Problem dims (fixed by the dataset)
#define BB 8
#define CC 19
#define HH 512
#define WW 1024
#define HWW (HH*WW)
#define NPIX (BB*HWW)

#define TS 32   // UF tile 32x32

// seam slot counts
#define NSEAM_H (BB * 15 * WW)          // 15 interior seam rows per image
#define NSEAM_V (BB * 31 * HH)          // 31 interior seam cols per image
#define NSEAM   (NSEAM_H + NSEAM_V)

// ---------------- scratch (device globals; no allocation allowed) ----------
__device__ int            g_parent[NPIX];
__device__ unsigned char  g_wmask[NPIX];   // bit0=weak, bit1=strong
__device__ unsigned char  g_flag[NPIX];    // root -> connected-to-strong
__device__ double         g_sum_nll;
__device__ double         g_sum_bnll;
__device__ unsigned long long g_cnt_valid;
__device__ unsigned long long g_cnt_b;

// ================= shared-memory union-find helpers ========================
__device__ __forceinline__ int find_s(int* sp, int x) {
    int p = sp[x];
    while (p != x) {
        int gp = sp[p];
        if (gp != p) sp[x] = gp;
        x = p; p = gp;
    }
    return x;
}

__device__ __forceinline__ void union_s(int* sp, int a, int b) {
    while (true) {
        a = find_s(sp, a);
        b = find_s(sp, b);
        if (a == b) return;
        if (a < b) { int t = a; a = b; b = t; }
        int old = atomicCAS(&sp[a], a, b);
        if (old == a) return;
        a = old;
    }
}

// ============ fused Sobel + NMS + threshold + tile-local UF ================
// 32x32 tile, 256 threads, 4 px/thread
__global__ __launch_bounds__(256) void k_canny(const int* __restrict__ tgt) {
    __shared__ float simg[TS + 4][TS + 5];   // img halo 2, edge-clamped (+pad)
    __shared__ float smag[TS + 2][TS + 3];   // mag halo 1, 0 outside img (+pad)
    __shared__ unsigned char ssec[TS][TS];   // quantized sector for centers
    __shared__ int sp[TS * TS];
    __shared__ unsigned char lw[TS * TS];

    const int tid = threadIdx.x;
    const int b  = blockIdx.z;
    const int h0 = blockIdx.y * TS;
    const int w0 = blockIdx.x * TS;
    const int* timg = tgt + b * HWW;
    const int base = b * HWW;

    // zero the accumulators once (k_canny completes before any reader runs)
    if (blockIdx.x == 0 && blockIdx.y == 0 && blockIdx.z == 0 && tid == 0) {
        g_sum_nll = 0.0; g_sum_bnll = 0.0; g_cnt_valid = 0ULL; g_cnt_b = 0ULL;
    }

    // load image (target*255)%256, edge padded
    for (int l = tid; l < (TS + 4) * (TS + 4); l += 256) {
        int rr = l / (TS + 4), cc = l - rr * (TS + 4);
        int gh = min(max(h0 - 2 + rr, 0), HH - 1);
        int gw = min(max(w0 - 2 + cc, 0), WW - 1);
        int t = __ldg(timg + gh * WW + gw);
        simg[rr][cc] = (float)((t * 255) & 255);
    }
    __syncthreads();

    // gradient once per halo-1 pixel: mag everywhere, sector for centers
    for (int l = tid; l < (TS + 2) * (TS + 2); l += 256) {
        int r = l / (TS + 2), c = l - r * (TS + 2);
        int gh = h0 - 1 + r, gw = w0 - 1 + c;
        float m = 0.f;
        float gx = 0.f, gy = 0.f;
        if (gh >= 0 && gh < HH && gw >= 0 && gw < WW) {
            float a00 = simg[r][c],     a01 = simg[r][c+1],     a02 = simg[r][c+2];
            float a10 = simg[r+1][c],                           a12 = simg[r+1][c+2];
            float a20 = simg[r+2][c],   a21 = simg[r+2][c+1],   a22 = simg[r+2][c+2];
            gx = (a02 + 2.f*a12 + a22) - (a00 + 2.f*a10 + a20);
            gy = (a20 + 2.f*a21 + a22) - (a00 + 2.f*a01 + a02);
            m = fabsf(gx) + fabsf(gy);
        }
        smag[r][c] = m;
        if (r >= 1 && r <= TS && c >= 1 && c <= TS) {
            float ax = fabsf(gx), ay = fabsf(gy);
            unsigned char sec;
            if (ay <= ax * 0.41421356f)      sec = 0;
            else if (ay >= ax * 2.41421356f) sec = 1;
            else sec = (gx * gy >= 0.f) ? 2 : 3;
            ssec[r - 1][c - 1] = sec;
        }
    }
    __syncthreads();

    // NMS + double threshold, 4 consecutive px per thread
    {
        int l0 = tid * 4;
        int lr = l0 >> 5, lcb = l0 & 31;
        uchar4 mout;
        unsigned char* mo = (unsigned char*)&mout;
#pragma unroll
        for (int k = 0; k < 4; k++) {
            int lc = lcb + k;
            int r = lr + 1, c = lc + 1;   // smag coords
            float mag = smag[r][c];
            unsigned char sec = ssec[lr][lc];
            float n1, n2;
            switch (sec) {
                case 0:  n1 = smag[r][c-1];   n2 = smag[r][c+1];   break;
                case 1:  n1 = smag[r-1][c];   n2 = smag[r+1][c];   break;
                case 2:  n1 = smag[r-1][c-1]; n2 = smag[r+1][c+1]; break;
                default: n1 = smag[r-1][c+1]; n2 = smag[r+1][c-1]; break;
            }
            bool keep = (mag >= n1) && (mag > n2);
            unsigned char m = 0;
            if (keep && mag > 50.f)  m |= 1;
            if (keep && mag > 150.f) m |= 2;
            mo[k] = m;
            lw[l0 + k] = m;
            sp[l0 + k] = l0 + k;
        }
        int gidx = base + (h0 + lr) * WW + w0 + lcb;
        *(uchar4*)(g_wmask + gidx) = mout;
        *(uchar4*)(g_flag  + gidx) = make_uchar4(0, 0, 0, 0);
    }
    __syncthreads();

    // local UF over weak pixels
#pragma unroll
    for (int k = 0; k < 4; k++) {
        int l = tid * 4 + k;
        if (!(lw[l] & 1)) continue;
        int lr = l >> 5, lc = l & 31;
        if (lc > 0 && (lw[l - 1] & 1)) union_s(sp, l, l - 1);
        if (lr > 0) {
            if (lw[l - 32] & 1)              union_s(sp, l, l - 32);
            if (lc > 0  && (lw[l - 33] & 1)) union_s(sp, l, l - 33);
            if (lc < 31 && (lw[l - 31] & 1)) union_s(sp, l, l - 31);
        }
    }
    __syncthreads();

    // write global parents (depth-1 tree: pixel -> tile-local root's global idx)
#pragma unroll
    for (int k = 0; k < 4; k++) {
        int l = tid * 4 + k;
        if (!(lw[l] & 1)) continue;
        int root = find_s(sp, l);
        int lr = l >> 5, lc = l & 31;
        int groot = base + (h0 + (root >> 5)) * WW + (w0 + (root & 31));
        g_parent[base + (h0 + lr) * WW + w0 + lc] = groot;
    }
}

// ================= global union-find helpers ===============================
__device__ __forceinline__ int uf_find(int* P, int x) {
    int p = P[x];
    while (p != x) {
        int gp = P[p];
        if (gp != p) P[x] = gp;
        x = p; p = gp;
    }
    return p;
}

__device__ __forceinline__ void uf_union(int* P, int a, int b) {
    while (true) {
        a = uf_find(P, a);
        b = uf_find(P, b);
        if (a == b) return;
        if (a < b) { int t = a; a = b; b = t; }
        int old = atomicCAS(&P[a], a, b);
        if (old == a) return;
        a = old;
    }
}

// ====== seam-direct cross-tile unions: one thread per seam pixel slot ======
// vertical part reindexed wi-fastest so a warp shares cache lines per row
__global__ __launch_bounds__(256) void k_seam() {
    int t = blockIdx.x * blockDim.x + threadIdx.x;
    if (t >= NSEAM) return;

    if (t < NSEAM_H) {
        // horizontal seams: rows h = 32,64,...,480 (15 per image), w fastest
        int b  = t / (15 * WW);
        int r  = t - b * (15 * WW);
        int hi = r / WW;
        int w  = r - hi * WW;
        int h  = (hi + 1) * TS;
        int base = b * HWW;
        int i = base + h * WW + w;
        if (!(g_wmask[i] & 1)) return;
        int rowup = base + (h - 1) * WW;
        if (g_wmask[rowup + w] & 1)                     uf_union(g_parent, i, rowup + w);
        if (w > 0      && (g_wmask[rowup + w - 1] & 1)) uf_union(g_parent, i, rowup + w - 1);
        if (w < WW - 1 && (g_wmask[rowup + w + 1] & 1)) uf_union(g_parent, i, rowup + w + 1);
    } else {
        // vertical seams: cols w = 32,64,...,992 (31 per image), wi FASTEST
        int t2 = t - NSEAM_H;
        int wi = t2 % 31;
        int r  = t2 / 31;
        int h  = r % HH;
        int b  = r / HH;
        int w  = (wi + 1) * TS;
        int base = b * HWW;
        int i = base + h * WW + w;       // pixel with lc==0
        bool iw  = (g_wmask[i] & 1) != 0;
        bool lw_ = (g_wmask[i - 1] & 1) != 0;    // (h, w-1), lc==31
        if (iw && lw_) uf_union(g_parent, i, i - 1);
        // diagonals across the vertical seam (horizontal-seam rows covered above)
        if ((h & (TS - 1)) != 0) {
            int up = i - WW;
            if (iw  && (g_wmask[up - 1] & 1)) uf_union(g_parent, i, up - 1);
            if (lw_ && (g_wmask[up] & 1))     uf_union(g_parent, i - 1, up);
        }
    }
}

// ====== mark: scan wmask, strong px only: find root, set flag ==============
__global__ __launch_bounds__(256) void k_mark() {
    int t = blockIdx.x * blockDim.x + threadIdx.x;
    int p0 = t * 16;
    if (p0 >= NPIX) return;
    uint4 mw = *(const uint4*)(g_wmask + p0);
    if (((mw.x | mw.y | mw.z | mw.w) & 0x02020202u) == 0u) return;
    unsigned char mb[16];
    *(uint4*)mb = mw;
#pragma unroll
    for (int k = 0; k < 16; k++) {
        if (!(mb[k] & 2)) continue;
        int root = uf_find(g_parent, p0 + k);
        g_flag[root] = 1;
    }
}

// ====== fused NLL + boundary reduce (flags ready; no g_nll round-trip) =====
__global__ __launch_bounds__(256, 4) void k_nllfused(const float* __restrict__ in,
                                                     const int* __restrict__ tgt) {
    const int tid = threadIdx.x;
    int p0 = (blockIdx.x * 256 + tid) * 4;
    int b = p0 / HWW;
    int off = p0 - b * HWW;
    const float* basep = in + (size_t)b * (CC * HWW) + off;

    int4 t4 = *(const int4*)(tgt + p0);
    int tg[4] = {t4.x, t4.y, t4.z, t4.w};

    float s[4]  = {0.f, 0.f, 0.f, 0.f};
    float xt[4] = {0.f, 0.f, 0.f, 0.f};

#pragma unroll 1
    for (int c0 = 0; c0 < CC; c0 += 5) {
        const int CN = (CC - c0 < 5) ? (CC - c0) : 5;
        float f[5][4];
#pragma unroll
        for (int j = 0; j < 5; j++) {
            if (j < CN) {
                float4 v = __ldg((const float4*)(basep + (size_t)(c0 + j) * HWW));
                f[j][0] = v.x; f[j][1] = v.y; f[j][2] = v.z; f[j][3] = v.w;
            }
        }
#pragma unroll
        for (int j = 0; j < 5; j++) {
            if (j < CN) {
#pragma unroll
                for (int k = 0; k < 4; k++) {
                    s[k] += __expf(f[j][k]);
                    if (c0 + j == tg[k]) xt[k] = f[j][k];
                }
            }
        }
    }

    uchar4 m4 = *(const uchar4*)(g_wmask + p0);
    unsigned char mm[4] = {m4.x, m4.y, m4.z, m4.w};

    double v1 = 0.0, v2 = 0.0;
    unsigned int cv = 0, cb = 0;
#pragma unroll
    for (int k = 0; k < 4; k++) {
        bool valid = (tg[k] != 255);
        float nll = valid ? (__logf(s[k]) - xt[k]) : 0.f;
        v1 += (double)nll;
        cv += valid ? 1u : 0u;
        if (mm[k] & 1) {
            // read-only root chase (trees are shallow: depth-1 + seam merges)
            int p = g_parent[p0 + k];
            int gp = g_parent[p];
            while (gp != p) { p = gp; gp = g_parent[p]; }
            if (g_flag[p]) { v2 += (double)nll; cb++; }
        }
    }

    const unsigned int full = 0xFFFFFFFFu;
#pragma unroll
    for (int o = 16; o > 0; o >>= 1) {
        v1 += __shfl_down_sync(full, v1, o);
        v2 += __shfl_down_sync(full, v2, o);
        cv += __shfl_down_sync(full, cv, o);
        cb += __shfl_down_sync(full, cb, o);
    }
    __shared__ double sh1[8], sh2[8];
    __shared__ unsigned int shc[8], shb[8];
    int lane = tid & 31, wid = tid >> 5;
    if (lane == 0) { sh1[wid] = v1; sh2[wid] = v2; shc[wid] = cv; shb[wid] = cb; }
    __syncthreads();
    if (wid == 0) {
        v1 = (lane < 8) ? sh1[lane] : 0.0;
        v2 = (lane < 8) ? sh2[lane] : 0.0;
        cv = (lane < 8) ? shc[lane] : 0u;
        cb = (lane < 8) ? shb[lane] : 0u;
#pragma unroll
        for (int o = 4; o > 0; o >>= 1) {
            v1 += __shfl_down_sync(full, v1, o);
            v2 += __shfl_down_sync(full, v2, o);
            cv += __shfl_down_sync(full, cv, o);
            cb += __shfl_down_sync(full, cb, o);
        }
        if (lane == 0) {
            atomicAdd(&g_sum_nll, v1);
            atomicAdd(&g_cnt_valid, (unsigned long long)cv);
            if (cb > 0 || v2 != 0.0) {
                atomicAdd(&g_sum_bnll, v2);
                atomicAdd(&g_cnt_b, (unsigned long long)cb);
            }
        }
    }
}

__global__ void k_final(float* __restrict__ out) {
    unsigned long long cv = g_cnt_valid;
    unsigned long long cb = g_cnt_b;
    double ce = g_sum_nll / (double)(cv > 0 ? cv : 1ULL);
    double loss = ce;
    if (cb > 0) loss += 10.0 * (g_sum_bnll / (double)cb);
    out[0] = (float)loss;
}

// ---------------- launch ---------------------------------------------------

extern "C" void kernel_launch(void* const* d_in, const int* in_sizes, int n_in,
                              void* d_out, int out_size) {
    const float* input  = (const float*)d_in[0];
    const int*   target = (const int*)d_in[1];
    float* out = (float*)d_out;

    k_canny<<<dim3(WW / TS, HH / TS, BB), 256>>>(target);
    k_seam<<<(NSEAM + 255) / 256, 256>>>();
    k_mark<<<NPIX / 16 / 256, 256>>>();
    k_nllfused<<<NPIX / 4 / 256, 256>>>(input, target);
    k_final<<<1, 1>>>(out);
}

// round 9
// speedup vs baseline: 1.0961x; 1.0961x over previous
#include <cuda_runtime.h>

// Problem dims (fixed by the dataset)
#define BB 8
#define CC 19
#define HH 512
#define WW 1024
#define HWW (HH*WW)
#define NPIX (BB*HWW)

#define TS 32   // UF tile 32x32

// seam slot counts
#define NSEAM_H (BB * 15 * WW)          // 15 interior seam rows per image
#define NSEAM_V (BB * 31 * HH)          // 31 interior seam cols per image
#define NSEAM   (NSEAM_H + NSEAM_V)

// ---------------- scratch (device globals; no allocation allowed) ----------
__device__ int            g_parent[NPIX];
__device__ unsigned char  g_wmask[NPIX];   // bit0=weak, bit1=strong
__device__ unsigned char  g_flag[NPIX];    // root -> connected-to-strong
__device__ double         g_sum_nll;
__device__ double         g_sum_bnll;
__device__ unsigned long long g_cnt_valid;
__device__ unsigned long long g_cnt_b;

// ================= shared-memory union-find helpers ========================
__device__ __forceinline__ int find_s(int* sp, int x) {
    int p = sp[x];
    while (p != x) {
        int gp = sp[p];
        if (gp != p) sp[x] = gp;
        x = p; p = gp;
    }
    return x;
}

__device__ __forceinline__ void union_s(int* sp, int a, int b) {
    while (true) {
        a = find_s(sp, a);
        b = find_s(sp, b);
        if (a == b) return;
        if (a < b) { int t = a; a = b; b = t; }
        int old = atomicCAS(&sp[a], a, b);
        if (old == a) return;
        a = old;
    }
}

// ============ fused Sobel + NMS + threshold + tile-local UF ================
// 32x32 tile, 256 threads, 4 px/thread
__global__ __launch_bounds__(256) void k_canny(const int* __restrict__ tgt) {
    __shared__ float simg[TS + 4][TS + 5];   // img halo 2, edge-clamped (+pad)
    __shared__ float smag[TS + 2][TS + 3];   // mag halo 1, 0 outside img (+pad)
    __shared__ unsigned char ssec[TS][TS];   // quantized sector for centers
    __shared__ int sp[TS * TS];
    __shared__ unsigned char lw[TS * TS];

    const int tid = threadIdx.x;
    const int b  = blockIdx.z;
    const int h0 = blockIdx.y * TS;
    const int w0 = blockIdx.x * TS;
    const int* timg = tgt + b * HWW;
    const int base = b * HWW;

    // zero the accumulators once (k_canny completes before any reader runs)
    if (blockIdx.x == 0 && blockIdx.y == 0 && blockIdx.z == 0 && tid == 0) {
        g_sum_nll = 0.0; g_sum_bnll = 0.0; g_cnt_valid = 0ULL; g_cnt_b = 0ULL;
    }

    // load image (target*255)%256, edge padded
    for (int l = tid; l < (TS + 4) * (TS + 4); l += 256) {
        int rr = l / (TS + 4), cc = l - rr * (TS + 4);
        int gh = min(max(h0 - 2 + rr, 0), HH - 1);
        int gw = min(max(w0 - 2 + cc, 0), WW - 1);
        int t = __ldg(timg + gh * WW + gw);
        simg[rr][cc] = (float)((t * 255) & 255);
    }
    __syncthreads();

    // gradient once per halo-1 pixel: mag everywhere, sector for centers
    for (int l = tid; l < (TS + 2) * (TS + 2); l += 256) {
        int r = l / (TS + 2), c = l - r * (TS + 2);
        int gh = h0 - 1 + r, gw = w0 - 1 + c;
        float m = 0.f;
        float gx = 0.f, gy = 0.f;
        if (gh >= 0 && gh < HH && gw >= 0 && gw < WW) {
            float a00 = simg[r][c],     a01 = simg[r][c+1],     a02 = simg[r][c+2];
            float a10 = simg[r+1][c],                           a12 = simg[r+1][c+2];
            float a20 = simg[r+2][c],   a21 = simg[r+2][c+1],   a22 = simg[r+2][c+2];
            gx = (a02 + 2.f*a12 + a22) - (a00 + 2.f*a10 + a20);
            gy = (a20 + 2.f*a21 + a22) - (a00 + 2.f*a01 + a02);
            m = fabsf(gx) + fabsf(gy);
        }
        smag[r][c] = m;
        if (r >= 1 && r <= TS && c >= 1 && c <= TS) {
            float ax = fabsf(gx), ay = fabsf(gy);
            unsigned char sec;
            if (ay <= ax * 0.41421356f)      sec = 0;
            else if (ay >= ax * 2.41421356f) sec = 1;
            else sec = (gx * gy >= 0.f) ? 2 : 3;
            ssec[r - 1][c - 1] = sec;
        }
    }
    __syncthreads();

    // NMS + double threshold, 4 consecutive px per thread
    {
        int l0 = tid * 4;
        int lr = l0 >> 5, lcb = l0 & 31;
        uchar4 mout;
        unsigned char* mo = (unsigned char*)&mout;
#pragma unroll
        for (int k = 0; k < 4; k++) {
            int lc = lcb + k;
            int r = lr + 1, c = lc + 1;   // smag coords
            float mag = smag[r][c];
            unsigned char sec = ssec[lr][lc];
            float n1, n2;
            switch (sec) {
                case 0:  n1 = smag[r][c-1];   n2 = smag[r][c+1];   break;
                case 1:  n1 = smag[r-1][c];   n2 = smag[r+1][c];   break;
                case 2:  n1 = smag[r-1][c-1]; n2 = smag[r+1][c+1]; break;
                default: n1 = smag[r-1][c+1]; n2 = smag[r+1][c-1]; break;
            }
            bool keep = (mag >= n1) && (mag > n2);
            unsigned char m = 0;
            if (keep && mag > 50.f)  m |= 1;
            if (keep && mag > 150.f) m |= 2;
            mo[k] = m;
            lw[l0 + k] = m;
            sp[l0 + k] = l0 + k;
        }
        int gidx = base + (h0 + lr) * WW + w0 + lcb;
        *(uchar4*)(g_wmask + gidx) = mout;
        *(uchar4*)(g_flag  + gidx) = make_uchar4(0, 0, 0, 0);
    }
    __syncthreads();

    // local UF over weak pixels
#pragma unroll
    for (int k = 0; k < 4; k++) {
        int l = tid * 4 + k;
        if (!(lw[l] & 1)) continue;
        int lr = l >> 5, lc = l & 31;
        if (lc > 0 && (lw[l - 1] & 1)) union_s(sp, l, l - 1);
        if (lr > 0) {
            if (lw[l - 32] & 1)              union_s(sp, l, l - 32);
            if (lc > 0  && (lw[l - 33] & 1)) union_s(sp, l, l - 33);
            if (lc < 31 && (lw[l - 31] & 1)) union_s(sp, l, l - 31);
        }
    }
    __syncthreads();

    // write global parents (depth-1 tree: pixel -> tile-local root's global idx)
#pragma unroll
    for (int k = 0; k < 4; k++) {
        int l = tid * 4 + k;
        if (!(lw[l] & 1)) continue;
        int root = find_s(sp, l);
        int lr = l >> 5, lc = l & 31;
        int groot = base + (h0 + (root >> 5)) * WW + (w0 + (root & 31));
        g_parent[base + (h0 + lr) * WW + w0 + lc] = groot;
    }
}

// ================= global union-find helpers ===============================
__device__ __forceinline__ int uf_find(int* P, int x) {
    int p = P[x];
    while (p != x) {
        int gp = P[p];
        if (gp != p) P[x] = gp;
        x = p; p = gp;
    }
    return p;
}

__device__ __forceinline__ void uf_union(int* P, int a, int b) {
    while (true) {
        a = uf_find(P, a);
        b = uf_find(P, b);
        if (a == b) return;
        if (a < b) { int t = a; a = b; b = t; }
        int old = atomicCAS(&P[a], a, b);
        if (old == a) return;
        a = old;
    }
}

// ====== seam-direct cross-tile unions: one thread per seam pixel slot ======
__global__ __launch_bounds__(256) void k_seam() {
    int t = blockIdx.x * blockDim.x + threadIdx.x;
    if (t >= NSEAM) return;

    if (t < NSEAM_H) {
        // horizontal seams: rows h = 32,64,...,480 (15 per image), w fastest
        int b  = t / (15 * WW);
        int r  = t - b * (15 * WW);
        int hi = r / WW;
        int w  = r - hi * WW;
        int h  = (hi + 1) * TS;
        int base = b * HWW;
        int i = base + h * WW + w;
        if (!(g_wmask[i] & 1)) return;
        int rowup = base + (h - 1) * WW;
        if (g_wmask[rowup + w] & 1)                     uf_union(g_parent, i, rowup + w);
        if (w > 0      && (g_wmask[rowup + w - 1] & 1)) uf_union(g_parent, i, rowup + w - 1);
        if (w < WW - 1 && (g_wmask[rowup + w + 1] & 1)) uf_union(g_parent, i, rowup + w + 1);
    } else {
        // vertical seams: cols w = 32,64,...,992 (31 per image), wi FASTEST
        int t2 = t - NSEAM_H;
        int wi = t2 % 31;
        int r  = t2 / 31;
        int h  = r % HH;
        int b  = r / HH;
        int w  = (wi + 1) * TS;
        int base = b * HWW;
        int i = base + h * WW + w;       // pixel with lc==0
        bool iw  = (g_wmask[i] & 1) != 0;
        bool lw_ = (g_wmask[i - 1] & 1) != 0;    // (h, w-1), lc==31
        if (iw && lw_) uf_union(g_parent, i, i - 1);
        // diagonals across the vertical seam (horizontal-seam rows covered above)
        if ((h & (TS - 1)) != 0) {
            int up = i - WW;
            if (iw  && (g_wmask[up - 1] & 1)) uf_union(g_parent, i, up - 1);
            if (lw_ && (g_wmask[up] & 1))     uf_union(g_parent, i - 1, up);
        }
    }
}

// ====== mark: scan wmask, strong px only: find root, set flag ==============
__global__ __launch_bounds__(256) void k_mark() {
    int t = blockIdx.x * blockDim.x + threadIdx.x;
    int p0 = t * 16;
    if (p0 >= NPIX) return;
    uint4 mw = *(const uint4*)(g_wmask + p0);
    if (((mw.x | mw.y | mw.z | mw.w) & 0x02020202u) == 0u) return;
    unsigned char mb[16];
    *(uint4*)mb = mw;
#pragma unroll
    for (int k = 0; k < 16; k++) {
        if (!(mb[k] & 2)) continue;
        int root = uf_find(g_parent, p0 + k);
        g_flag[root] = 1;
    }
}

// ====== fused NLL + boundary reduce, software-pipelined channel loads ======
__device__ __forceinline__ void nll_load(float f[4][4], const float* basep,
                                         int c0, int cn) {
#pragma unroll
    for (int j = 0; j < 4; j++) {
        if (j < cn) {
            float4 v = __ldcs((const float4*)(basep + (size_t)(c0 + j) * HWW));
            f[j][0] = v.x; f[j][1] = v.y; f[j][2] = v.z; f[j][3] = v.w;
        }
    }
}

__device__ __forceinline__ void nll_compute(const float f[4][4], const int tg[4],
                                            float s[4], float xt[4],
                                            int c0, int cn) {
#pragma unroll
    for (int j = 0; j < 4; j++) {
        if (j < cn) {
#pragma unroll
            for (int k = 0; k < 4; k++) {
                s[k] += __expf(f[j][k]);
                if (c0 + j == tg[k]) xt[k] = f[j][k];
            }
        }
    }
}

__global__ __launch_bounds__(256, 4) void k_nllfused(const float* __restrict__ in,
                                                     const int* __restrict__ tgt) {
    const int tid = threadIdx.x;
    int p0 = (blockIdx.x * 256 + tid) * 4;
    int b = p0 / HWW;
    int off = p0 - b * HWW;
    const float* basep = in + (size_t)b * (CC * HWW) + off;

    int4 t4 = *(const int4*)(tgt + p0);
    int tg[4] = {t4.x, t4.y, t4.z, t4.w};

    float s[4]  = {0.f, 0.f, 0.f, 0.f};
    float xt[4] = {0.f, 0.f, 0.f, 0.f};

    // double-buffered pipeline over 5 chunks: 4+4+4+4+3 channels
    float A[4][4], B[4][4];
    nll_load(A, basep, 0, 4);
    nll_load(B, basep, 4, 4);  nll_compute(A, tg, s, xt, 0, 4);
    nll_load(A, basep, 8, 4);  nll_compute(B, tg, s, xt, 4, 4);
    nll_load(B, basep, 12, 4); nll_compute(A, tg, s, xt, 8, 4);
    nll_load(A, basep, 16, 3); nll_compute(B, tg, s, xt, 12, 4);
    nll_compute(A, tg, s, xt, 16, 3);

    uchar4 m4 = *(const uchar4*)(g_wmask + p0);
    unsigned char mm[4] = {m4.x, m4.y, m4.z, m4.w};

    double v1 = 0.0, v2 = 0.0;
    unsigned int cv = 0, cb = 0;
#pragma unroll
    for (int k = 0; k < 4; k++) {
        bool valid = (tg[k] != 255);
        float nll = valid ? (__logf(s[k]) - xt[k]) : 0.f;
        v1 += (double)nll;
        cv += valid ? 1u : 0u;
        if (mm[k] & 1) {
            // read-only root chase (trees are shallow: depth-1 + seam merges)
            int p = g_parent[p0 + k];
            int gp = g_parent[p];
            while (gp != p) { p = gp; gp = g_parent[p]; }
            if (g_flag[p]) { v2 += (double)nll; cb++; }
        }
    }

    const unsigned int full = 0xFFFFFFFFu;
#pragma unroll
    for (int o = 16; o > 0; o >>= 1) {
        v1 += __shfl_down_sync(full, v1, o);
        v2 += __shfl_down_sync(full, v2, o);
        cv += __shfl_down_sync(full, cv, o);
        cb += __shfl_down_sync(full, cb, o);
    }
    __shared__ double sh1[8], sh2[8];
    __shared__ unsigned int shc[8], shb[8];
    int lane = tid & 31, wid = tid >> 5;
    if (lane == 0) { sh1[wid] = v1; sh2[wid] = v2; shc[wid] = cv; shb[wid] = cb; }
    __syncthreads();
    if (wid == 0) {
        v1 = (lane < 8) ? sh1[lane] : 0.0;
        v2 = (lane < 8) ? sh2[lane] : 0.0;
        cv = (lane < 8) ? shc[lane] : 0u;
        cb = (lane < 8) ? shb[lane] : 0u;
#pragma unroll
        for (int o = 4; o > 0; o >>= 1) {
            v1 += __shfl_down_sync(full, v1, o);
            v2 += __shfl_down_sync(full, v2, o);
            cv += __shfl_down_sync(full, cv, o);
            cb += __shfl_down_sync(full, cb, o);
        }
        if (lane == 0) {
            atomicAdd(&g_sum_nll, v1);
            atomicAdd(&g_cnt_valid, (unsigned long long)cv);
            if (cb > 0 || v2 != 0.0) {
                atomicAdd(&g_sum_bnll, v2);
                atomicAdd(&g_cnt_b, (unsigned long long)cb);
            }
        }
    }
}

__global__ void k_final(float* __restrict__ out) {
    unsigned long long cv = g_cnt_valid;
    unsigned long long cb = g_cnt_b;
    double ce = g_sum_nll / (double)(cv > 0 ? cv : 1ULL);
    double loss = ce;
    if (cb > 0) loss += 10.0 * (g_sum_bnll / (double)cb);
    out[0] = (float)loss;
}

// ---------------- launch ---------------------------------------------------

extern "C" void kernel_launch(void* const* d_in, const int* in_sizes, int n_in,
                              void* d_out, int out_size) {
    const float* input  = (const float*)d_in[0];
    const int*   target = (const int*)d_in[1];
    float* out = (float*)d_out;

    k_canny<<<dim3(WW / TS, HH / TS, BB), 256>>>(target);
    k_seam<<<(NSEAM + 255) / 256, 256>>>();
    k_mark<<<NPIX / 16 / 256, 256>>>();
    k_nllfused<<<NPIX / 4 / 256, 256>>>(input, target);
    k_final<<<1, 1>>>(out);
}